// round 1
// baseline (speedup 1.0000x reference)
#include <cuda_runtime.h>
#include <math.h>

#define Bb 8
#define Ss 4096
#define Dd 2048
#define N_ITEMS 8192
#define KTOP 64

// ---- device scratch (no allocation allowed) ----
__device__ float g_qsum[Bb][Dd];
__device__ float g_q[Bb][Dd];
__device__ float g_sims[Bb][N_ITEMS];
__device__ int   g_last[Bb];

// Kernel A: zero g_qsum and compute last-valid-token index per batch.
// grid 32 x 512 threads (32*512 == Bb*Dd).
__global__ void k_init(const unsigned char* __restrict__ mask) {
    int t = threadIdx.x;
    ((float*)g_qsum)[blockIdx.x * 512 + t] = 0.0f;
    if (blockIdx.x < Bb) {
        int b = blockIdx.x;
        int s = 0;
        for (int i = t; i < Ss; i += 512) s += (int)mask[b * Ss + i];
        __shared__ int red[16];
        for (int o = 16; o > 0; o >>= 1) s += __shfl_down_sync(0xffffffffu, s, o);
        if ((t & 31) == 0) red[t >> 5] = s;
        __syncthreads();
        if (t == 0) {
            int tot = 0;
            #pragma unroll
            for (int w = 0; w < 16; w++) tot += red[w];
            g_last[b] = max(tot, 1) - 1;
        }
    }
}

// Kernel B: copy x -> out (float4) fused with masked per-(b,d) column sums.
// grid: (Dd/512, 64, Bb), 128 threads, each thread: float4 column over 64 s-rows.
__global__ void __launch_bounds__(128) k_copy_reduce(
    const float* __restrict__ x, const unsigned char* __restrict__ mask,
    float* __restrict__ out) {
    const int b  = blockIdx.z;
    const int d0 = blockIdx.x * 512 + threadIdx.x * 4;
    const int s0 = blockIdx.y * (Ss / 64);
    const size_t base = (size_t)b * Ss * Dd + (size_t)s0 * Dd + d0;
    const float4* __restrict__ xp = (const float4*)(x + base);
    float4* __restrict__ op = (float4*)(out + base);
    const unsigned char* __restrict__ mp = mask + b * Ss + s0;

    float4 acc = make_float4(0.f, 0.f, 0.f, 0.f);
    #pragma unroll 4
    for (int s = 0; s < Ss / 64; s++) {
        float4 v = xp[(size_t)s * (Dd / 4)];
        op[(size_t)s * (Dd / 4)] = v;
        float m = (float)mp[s];
        acc.x += v.x * m; acc.y += v.y * m; acc.z += v.z * m; acc.w += v.w * m;
    }
    float* qs = &g_qsum[b][d0];
    atomicAdd(qs + 0, acc.x);
    atomicAdd(qs + 1, acc.y);
    atomicAdd(qs + 2, acc.z);
    atomicAdd(qs + 3, acc.w);
}

// Kernel C: q = normalize(qsum). (lengths cancel under L2 normalization)
// grid Bb x 256 threads.
__global__ void k_norm_q() {
    int b = blockIdx.x, t = threadIdx.x;
    float ss = 0.f;
    for (int d = t; d < Dd; d += 256) { float v = g_qsum[b][d]; ss += v * v; }
    __shared__ float red[8];
    for (int o = 16; o > 0; o >>= 1) ss += __shfl_down_sync(0xffffffffu, ss, o);
    if ((t & 31) == 0) red[t >> 5] = ss;
    __syncthreads();
    __shared__ float s_inv;
    if (t == 0) {
        float tot = 0.f;
        #pragma unroll
        for (int w = 0; w < 8; w++) tot += red[w];
        float nrm = sqrtf(tot);
        s_inv = 1.0f / fmaxf(nrm, 1e-12f);
    }
    __syncthreads();
    float inv = s_inv;
    for (int d = t; d < Dd; d += 256) g_q[b][d] = g_qsum[b][d] * inv;
}

// Kernel D: sims[b][n] = (q_b . k_n) / max(||k_n||, eps). One warp per key row.
// grid 256 x 256 threads, 64KB dynamic smem for q.
__global__ void __launch_bounds__(256) k_sims(const float* __restrict__ keys) {
    extern __shared__ float sq[];  // [Bb][Dd]
    for (int i = threadIdx.x; i < Bb * Dd; i += blockDim.x)
        sq[i] = ((const float*)g_q)[i];
    __syncthreads();

    const int warp = threadIdx.x >> 5, lane = threadIdx.x & 31;
    const int nwarp = blockDim.x >> 5;  // 8
    for (int n = blockIdx.x * nwarp + warp; n < N_ITEMS; n += gridDim.x * nwarp) {
        const float4* __restrict__ kp = (const float4*)(keys + (size_t)n * Dd);
        float ssq = 0.f;
        float dot[Bb];
        #pragma unroll
        for (int bb = 0; bb < Bb; bb++) dot[bb] = 0.f;

        for (int i = lane; i < Dd / 4; i += 32) {
            float4 kv = kp[i];
            ssq += kv.x * kv.x + kv.y * kv.y + kv.z * kv.z + kv.w * kv.w;
            #pragma unroll
            for (int bb = 0; bb < Bb; bb++) {
                float4 qv = ((const float4*)(sq + bb * Dd))[i];
                dot[bb] += kv.x * qv.x + kv.y * qv.y + kv.z * qv.z + kv.w * qv.w;
            }
        }
        for (int o = 16; o > 0; o >>= 1) {
            ssq += __shfl_down_sync(0xffffffffu, ssq, o);
            #pragma unroll
            for (int bb = 0; bb < Bb; bb++)
                dot[bb] += __shfl_down_sync(0xffffffffu, dot[bb], o);
        }
        if (lane == 0) {
            float nrm = sqrtf(ssq);
            float inv = 1.0f / fmaxf(nrm, 1e-12f);
            #pragma unroll
            for (int bb = 0; bb < Bb; bb++) g_sims[bb][n] = dot[bb] * inv;
        }
    }
}

// Kernel E: per batch: top-64 (iterative argmax), softmax(T=0.03), gated
// retrieval over gathered value rows, add delta to out[b, last, :].
// grid Bb x 256 threads.
__global__ void __launch_bounds__(256) k_topk_update(
    const float* __restrict__ values, float* __restrict__ out) {
    const int b = blockIdx.x, t = threadIdx.x;
    __shared__ float sv[N_ITEMS];        // 32KB
    __shared__ float topv[KTOP];
    __shared__ int   topi[KTOP];
    __shared__ float redv[8];
    __shared__ int   redi[8];
    __shared__ float w[KTOP];
    __shared__ float s_scale;

    for (int i = t; i < N_ITEMS; i += 256) sv[i] = g_sims[b][i];
    __syncthreads();

    for (int k = 0; k < KTOP; k++) {
        float m = -INFINITY; int mi = 0;
        for (int i = t; i < N_ITEMS; i += 256) {
            float v = sv[i];
            if (v > m) { m = v; mi = i; }
        }
        for (int o = 16; o > 0; o >>= 1) {
            float ov = __shfl_down_sync(0xffffffffu, m, o);
            int   oi = __shfl_down_sync(0xffffffffu, mi, o);
            if (ov > m) { m = ov; mi = oi; }
        }
        if ((t & 31) == 0) { redv[t >> 5] = m; redi[t >> 5] = mi; }
        __syncthreads();
        if (t == 0) {
            #pragma unroll
            for (int ww = 1; ww < 8; ww++)
                if (redv[ww] > m) { m = redv[ww]; mi = redi[ww]; }
            topv[k] = m; topi[k] = mi;
            sv[mi] = -INFINITY;
        }
        __syncthreads();
    }

    if (t < KTOP) {
        float m0 = topv[0];
        w[t] = __expf((topv[t] - m0) * (1.0f / 0.03f));
    }
    __syncthreads();
    if (t == 0) {
        float sum = 0.f;
        #pragma unroll
        for (int k = 0; k < KTOP; k++) sum += w[k];
        float m0 = topv[0];
        float gate = 1.0f / (1.0f + __expf(-(m0 - 0.85f) * 40.0f));
        s_scale = 16.0f * gate / sum;
    }
    __syncthreads();

    const float scale = s_scale;
    const int last = g_last[b];
    float* __restrict__ op = out + (size_t)b * Ss * Dd + (size_t)last * Dd;

    for (int d = t * 4; d < Dd; d += 256 * 4) {
        float4 acc = make_float4(0.f, 0.f, 0.f, 0.f);
        #pragma unroll 8
        for (int k = 0; k < KTOP; k++) {
            float4 vv = *(const float4*)(values + (size_t)topi[k] * Dd + d);
            float wk = w[k];
            acc.x += wk * vv.x; acc.y += wk * vv.y;
            acc.z += wk * vv.z; acc.w += wk * vv.w;
        }
        float4 cur = *(float4*)(op + d);
        cur.x += scale * acc.x; cur.y += scale * acc.y;
        cur.z += scale * acc.z; cur.w += scale * acc.w;
        *(float4*)(op + d) = cur;
    }
}

extern "C" void kernel_launch(void* const* d_in, const int* in_sizes, int n_in,
                              void* d_out, int out_size) {
    const float*         x    = (const float*)d_in[0];
    const unsigned char* mask = (const unsigned char*)d_in[1];
    const float*         keys = (const float*)d_in[2];
    const float*         vals = (const float*)d_in[3];
    float* out = (float*)d_out;

    // allow 64KB dynamic smem for k_sims (host attribute set; idempotent)
    cudaFuncSetAttribute(k_sims, cudaFuncAttributeMaxDynamicSharedMemorySize,
                         Bb * Dd * (int)sizeof(float));

    k_init<<<32, 512>>>(mask);
    k_copy_reduce<<<dim3(Dd / 512, 64, Bb), 128>>>(x, mask, out);
    k_norm_q<<<Bb, 256>>>();
    k_sims<<<256, 256, Bb * Dd * sizeof(float)>>>(keys);
    k_topk_update<<<Bb, 256>>>(vals, out);
}

// round 2
// speedup vs baseline: 1.2536x; 1.2536x over previous
#include <cuda_runtime.h>
#include <math.h>

#define Bb 8
#define Ss 4096
#define Dd 2048
#define N_ITEMS 8192
#define KTOP 64
#define SCHUNKS 64
#define SROWS (Ss / SCHUNKS)   // 64 rows per chunk

// ---- device scratch (static; every word rewritten every launch -> replay-safe) ----
__device__ float g_part[SCHUNKS][Bb][Dd];   // 4MB partial masked sums
__device__ float g_q[Bb][Dd];
__device__ float g_sims[Bb][N_ITEMS];

// ---------------------------------------------------------------------------
// Kernel 1: copy x -> out (streaming) fused with masked partial column sums.
// grid (Dd/1024, SCHUNKS, Bb) x 256 threads. Each thread: one float4 column
// over SROWS rows; partial sum written non-atomically to g_part.
// ---------------------------------------------------------------------------
__global__ void __launch_bounds__(256) k_copy_reduce(
    const float* __restrict__ x, const unsigned char* __restrict__ mask,
    float* __restrict__ out) {
    const int b  = blockIdx.z;
    const int d0 = blockIdx.x * 1024 + threadIdx.x * 4;
    const int s0 = blockIdx.y * SROWS;
    const size_t base = (size_t)b * Ss * Dd + (size_t)s0 * Dd + d0;
    const float4* __restrict__ xp = (const float4*)(x + base);
    float4* __restrict__ op = (float4*)(out + base);
    const unsigned char* __restrict__ mp = mask + b * Ss + s0;

    float4 acc = make_float4(0.f, 0.f, 0.f, 0.f);
    #pragma unroll 8
    for (int s = 0; s < SROWS; s++) {
        float4 v = __ldcs(&xp[(size_t)s * (Dd / 4)]);
        __stcs(&op[(size_t)s * (Dd / 4)], v);
        float m = (float)mp[s];
        acc.x += v.x * m; acc.y += v.y * m; acc.z += v.z * m; acc.w += v.w * m;
    }
    *(float4*)&g_part[blockIdx.y][b][d0] = acc;
}

// ---------------------------------------------------------------------------
// Kernel 2: reduce partials, L2-normalize -> g_q. grid Bb x 512.
// (mean scale cancels under L2 normalization)
// ---------------------------------------------------------------------------
__global__ void __launch_bounds__(512) k_qnorm() {
    const int b = blockIdx.x, t = threadIdx.x;
    const int d0 = t * 4;
    float4 acc = make_float4(0.f, 0.f, 0.f, 0.f);
    #pragma unroll 8
    for (int c = 0; c < SCHUNKS; c++) {
        float4 p = *(const float4*)&g_part[c][b][d0];
        acc.x += p.x; acc.y += p.y; acc.z += p.z; acc.w += p.w;
    }
    float ss = acc.x * acc.x + acc.y * acc.y + acc.z * acc.z + acc.w * acc.w;
    __shared__ float red[16];
    for (int o = 16; o > 0; o >>= 1) ss += __shfl_down_sync(0xffffffffu, ss, o);
    if ((t & 31) == 0) red[t >> 5] = ss;
    __syncthreads();
    __shared__ float s_inv;
    if (t == 0) {
        float tot = 0.f;
        #pragma unroll
        for (int w = 0; w < 16; w++) tot += red[w];
        s_inv = 1.0f / fmaxf(sqrtf(tot), 1e-12f);
    }
    __syncthreads();
    const float inv = s_inv;
    float4 q = make_float4(acc.x * inv, acc.y * inv, acc.z * inv, acc.w * inv);
    *(float4*)&g_q[b][d0] = q;
}

// ---------------------------------------------------------------------------
// Kernel 3: sims. 256 blocks x 256 threads; each warp handles 4 consecutive
// keys (MLP=4 on the global stream, q smem loads amortized 4x). q in 64KB smem.
// ---------------------------------------------------------------------------
__global__ void __launch_bounds__(256) k_sims(const float* __restrict__ keys) {
    extern __shared__ float sq[];  // [Bb][Dd] = 64KB
    for (int i = threadIdx.x; i < Bb * Dd / 4; i += blockDim.x)
        ((float4*)sq)[i] = ((const float4*)g_q)[i];
    __syncthreads();

    const int warp = threadIdx.x >> 5, lane = threadIdx.x & 31;
    const int n0 = (blockIdx.x * 8 + warp) * 4;   // 4 keys per warp

    const float4* __restrict__ k0 = (const float4*)(keys + (size_t)(n0 + 0) * Dd);
    const float4* __restrict__ k1 = (const float4*)(keys + (size_t)(n0 + 1) * Dd);
    const float4* __restrict__ k2 = (const float4*)(keys + (size_t)(n0 + 2) * Dd);
    const float4* __restrict__ k3 = (const float4*)(keys + (size_t)(n0 + 3) * Dd);

    float dot[4][Bb];
    float ssq[4] = {0.f, 0.f, 0.f, 0.f};
    #pragma unroll
    for (int j = 0; j < 4; j++)
        #pragma unroll
        for (int bb = 0; bb < Bb; bb++) dot[j][bb] = 0.f;

    #pragma unroll 2
    for (int i = lane; i < Dd / 4; i += 32) {
        float4 kv[4];
        kv[0] = __ldcs(&k0[i]); kv[1] = __ldcs(&k1[i]);
        kv[2] = __ldcs(&k2[i]); kv[3] = __ldcs(&k3[i]);
        #pragma unroll
        for (int j = 0; j < 4; j++)
            ssq[j] += kv[j].x * kv[j].x + kv[j].y * kv[j].y
                    + kv[j].z * kv[j].z + kv[j].w * kv[j].w;
        #pragma unroll
        for (int bb = 0; bb < Bb; bb++) {
            float4 qv = ((const float4*)(sq + bb * Dd))[i];
            #pragma unroll
            for (int j = 0; j < 4; j++)
                dot[j][bb] += kv[j].x * qv.x + kv[j].y * qv.y
                            + kv[j].z * qv.z + kv[j].w * qv.w;
        }
    }
    #pragma unroll
    for (int o = 16; o > 0; o >>= 1) {
        #pragma unroll
        for (int j = 0; j < 4; j++) {
            ssq[j] += __shfl_down_sync(0xffffffffu, ssq[j], o);
            #pragma unroll
            for (int bb = 0; bb < Bb; bb++)
                dot[j][bb] += __shfl_down_sync(0xffffffffu, dot[j][bb], o);
        }
    }
    if (lane == 0) {
        #pragma unroll
        for (int j = 0; j < 4; j++) {
            float inv = 1.0f / fmaxf(sqrtf(ssq[j]), 1e-12f);
            #pragma unroll
            for (int bb = 0; bb < Bb; bb++) g_sims[bb][n0 + j] = dot[j][bb] * inv;
        }
    }
}

// ---------------------------------------------------------------------------
// Kernel 4: per batch: last-index from mask, top-64 via register-cached
// iterative argmax, softmax(T=0.03), gated retrieval, update out[b,last,:].
// grid Bb x 512 threads. 16 sims cached in regs per thread.
// ---------------------------------------------------------------------------
__global__ void __launch_bounds__(512) k_topk_update(
    const unsigned char* __restrict__ mask,
    const float* __restrict__ values, float* __restrict__ out) {
    const int b = blockIdx.x, t = threadIdx.x;
    const int w = t >> 5, lane = t & 31;

    __shared__ float lv[512];
    __shared__ int   li[512];
    __shared__ float wv[16];
    __shared__ int   wi[16], wt[16];
    __shared__ float topv[KTOP];
    __shared__ int   topi[KTOP];
    __shared__ float s_w[KTOP];
    __shared__ float s_scale;
    __shared__ int   s_bestt, s_bestw;
    __shared__ int   redc[16];

    // ---- last valid index ----
    int cnt = 0;
    for (int i = t; i < Ss; i += 512) cnt += (int)mask[b * Ss + i];
    for (int o = 16; o > 0; o >>= 1) cnt += __shfl_down_sync(0xffffffffu, cnt, o);
    if (lane == 0) redc[w] = cnt;

    // ---- cache sims in registers ----
    float v[16];
    float m = -INFINITY; int mi = -1;
    #pragma unroll
    for (int j = 0; j < 16; j++) {
        v[j] = g_sims[b][t + j * 512];
        if (v[j] > m) { m = v[j]; mi = t + j * 512; }
    }
    lv[t] = m; li[t] = mi;
    // per-warp argmax (carry owner tid)
    {
        float bm = m; int bi = mi, bt = t;
        #pragma unroll
        for (int o = 16; o > 0; o >>= 1) {
            float ov = __shfl_down_sync(0xffffffffu, bm, o);
            int oi = __shfl_down_sync(0xffffffffu, bi, o);
            int ot = __shfl_down_sync(0xffffffffu, bt, o);
            if (ov > bm) { bm = ov; bi = oi; bt = ot; }
        }
        if (lane == 0) { wv[w] = bm; wi[w] = bi; wt[w] = bt; }
    }
    __syncthreads();

    // ---- 64 x argmax-extract ----
    for (int k = 0; k < KTOP; k++) {
        if (t < 32) {
            float bm = (lane < 16) ? wv[lane] : -INFINITY;
            int bi = (lane < 16) ? wi[lane] : -1;
            int bt = (lane < 16) ? wt[lane] : 0;
            int bw = lane;
            #pragma unroll
            for (int o = 8; o > 0; o >>= 1) {
                float ov = __shfl_down_sync(0xffffffffu, bm, o);
                int oi = __shfl_down_sync(0xffffffffu, bi, o);
                int ot = __shfl_down_sync(0xffffffffu, bt, o);
                int ow = __shfl_down_sync(0xffffffffu, bw, o);
                if (ov > bm) { bm = ov; bi = oi; bt = ot; bw = ow; }
            }
            if (lane == 0) {
                topv[k] = bm; topi[k] = bi; s_bestt = bt; s_bestw = bw;
            }
        }
        __syncthreads();
        const int bt = s_bestt, bw = s_bestw;
        if (t == bt) {
            int j = (topi[k] - t) >> 9;   // idx = t + j*512
            v[j] = -INFINITY;
            float nm = -INFINITY; int nmi = -1;
            #pragma unroll
            for (int jj = 0; jj < 16; jj++)
                if (v[jj] > nm) { nm = v[jj]; nmi = t + jj * 512; }
            lv[t] = nm; li[t] = nmi;
        }
        __syncthreads();
        if (w == bw) {
            float bm = lv[t]; int bi = li[t], btd = t;
            #pragma unroll
            for (int o = 16; o > 0; o >>= 1) {
                float ov = __shfl_down_sync(0xffffffffu, bm, o);
                int oi = __shfl_down_sync(0xffffffffu, bi, o);
                int ot = __shfl_down_sync(0xffffffffu, btd, o);
                if (ov > bm) { bm = ov; bi = oi; btd = ot; }
            }
            if (lane == 0) { wv[w] = bm; wi[w] = bi; wt[w] = btd; }
        }
        __syncthreads();
    }

    // ---- softmax weights + gate ----
    if (t < KTOP) s_w[t] = __expf((topv[t] - topv[0]) * (1.0f / 0.03f));
    __syncthreads();
    if (t == 0) {
        float sum = 0.f;
        #pragma unroll
        for (int k = 0; k < KTOP; k++) sum += s_w[k];
        float gate = 1.0f / (1.0f + __expf(-(topv[0] - 0.85f) * 40.0f));
        s_scale = 16.0f * gate / sum;
        int tot = 0;
        #pragma unroll
        for (int ww = 0; ww < 16; ww++) tot += redc[ww];
        redc[0] = max(tot, 1) - 1;   // reuse as s_last
    }
    __syncthreads();

    // ---- gather weighted values, update out[b,last,:] ----
    const float scale = s_scale;
    const int last = redc[0];
    float* __restrict__ op = out + (size_t)b * Ss * Dd + (size_t)last * Dd + t * 4;

    float4 acc = make_float4(0.f, 0.f, 0.f, 0.f);
    #pragma unroll 8
    for (int k = 0; k < KTOP; k++) {
        const float4 vv = *(const float4*)(values + (size_t)topi[k] * Dd + t * 4);
        const float wk = s_w[k];
        acc.x += wk * vv.x; acc.y += wk * vv.y;
        acc.z += wk * vv.z; acc.w += wk * vv.w;
    }
    float4 cur = *(float4*)op;
    cur.x += scale * acc.x; cur.y += scale * acc.y;
    cur.z += scale * acc.z; cur.w += scale * acc.w;
    *(float4*)op = cur;
}

extern "C" void kernel_launch(void* const* d_in, const int* in_sizes, int n_in,
                              void* d_out, int out_size) {
    const float*         x    = (const float*)d_in[0];
    const unsigned char* mask = (const unsigned char*)d_in[1];
    const float*         keys = (const float*)d_in[2];
    const float*         vals = (const float*)d_in[3];
    float* out = (float*)d_out;

    cudaFuncSetAttribute(k_sims, cudaFuncAttributeMaxDynamicSharedMemorySize,
                         Bb * Dd * (int)sizeof(float));

    k_copy_reduce<<<dim3(Dd / 1024, SCHUNKS, Bb), 256>>>(x, mask, out);
    k_qnorm<<<Bb, 512>>>();
    k_sims<<<256, 256, Bb * Dd * sizeof(float)>>>(keys);
    k_topk_update<<<Bb, 512>>>(mask, vals, out);
}

// round 3
// speedup vs baseline: 1.4759x; 1.1773x over previous
#include <cuda_runtime.h>
#include <math.h>

#define Bb 8
#define Ss 4096
#define Dd 2048
#define N_ITEMS 8192
#define KTOP 64
#define SCHUNKS 64
#define SROWS (Ss / SCHUNKS)   // 64 rows per chunk

// ---- device scratch (static; every word rewritten every launch -> replay-safe) ----
__device__ float g_part[SCHUNKS][Bb][Dd];   // 4MB partial masked sums
__device__ float g_q[Bb][Dd];
__device__ float g_sims[Bb][N_ITEMS];

// ---------------------------------------------------------------------------
// Kernel 1: copy x -> out (streaming) fused with masked partial column sums.
// ---------------------------------------------------------------------------
__global__ void __launch_bounds__(256) k_copy_reduce(
    const float* __restrict__ x, const unsigned char* __restrict__ mask,
    float* __restrict__ out) {
    const int b  = blockIdx.z;
    const int d0 = blockIdx.x * 1024 + threadIdx.x * 4;
    const int s0 = blockIdx.y * SROWS;
    const size_t base = (size_t)b * Ss * Dd + (size_t)s0 * Dd + d0;
    const float4* __restrict__ xp = (const float4*)(x + base);
    float4* __restrict__ op = (float4*)(out + base);
    const unsigned char* __restrict__ mp = mask + b * Ss + s0;

    float4 acc = make_float4(0.f, 0.f, 0.f, 0.f);
    #pragma unroll 8
    for (int s = 0; s < SROWS; s++) {
        float4 v = __ldcs(&xp[(size_t)s * (Dd / 4)]);
        __stcs(&op[(size_t)s * (Dd / 4)], v);
        float m = (float)mp[s];
        acc.x += v.x * m; acc.y += v.y * m; acc.z += v.z * m; acc.w += v.w * m;
    }
    *(float4*)&g_part[blockIdx.y][b][d0] = acc;
}

// ---------------------------------------------------------------------------
// Kernel 2: reduce partials, L2-normalize -> g_q. grid Bb x 512.
// ---------------------------------------------------------------------------
__global__ void __launch_bounds__(512) k_qnorm() {
    const int b = blockIdx.x, t = threadIdx.x;
    const int d0 = t * 4;
    float4 acc = make_float4(0.f, 0.f, 0.f, 0.f);
    #pragma unroll 8
    for (int c = 0; c < SCHUNKS; c++) {
        float4 p = *(const float4*)&g_part[c][b][d0];
        acc.x += p.x; acc.y += p.y; acc.z += p.z; acc.w += p.w;
    }
    float ss = acc.x * acc.x + acc.y * acc.y + acc.z * acc.z + acc.w * acc.w;
    __shared__ float red[16];
    for (int o = 16; o > 0; o >>= 1) ss += __shfl_down_sync(0xffffffffu, ss, o);
    if ((t & 31) == 0) red[t >> 5] = ss;
    __syncthreads();
    __shared__ float s_inv;
    if (t == 0) {
        float tot = 0.f;
        #pragma unroll
        for (int w = 0; w < 16; w++) tot += red[w];
        s_inv = 1.0f / fmaxf(sqrtf(tot), 1e-12f);
    }
    __syncthreads();
    const float inv = s_inv;
    float4 q = make_float4(acc.x * inv, acc.y * inv, acc.z * inv, acc.w * inv);
    *(float4*)&g_q[b][d0] = q;
}

// ---------------------------------------------------------------------------
// Kernel 3: sims. 256 blocks x 256 threads; 4 keys per warp. q in 64KB smem.
// ---------------------------------------------------------------------------
__global__ void __launch_bounds__(256) k_sims(const float* __restrict__ keys) {
    extern __shared__ float sq[];  // [Bb][Dd] = 64KB
    for (int i = threadIdx.x; i < Bb * Dd / 4; i += blockDim.x)
        ((float4*)sq)[i] = ((const float4*)g_q)[i];
    __syncthreads();

    const int warp = threadIdx.x >> 5, lane = threadIdx.x & 31;
    const int n0 = (blockIdx.x * 8 + warp) * 4;

    const float4* __restrict__ k0 = (const float4*)(keys + (size_t)(n0 + 0) * Dd);
    const float4* __restrict__ k1 = (const float4*)(keys + (size_t)(n0 + 1) * Dd);
    const float4* __restrict__ k2 = (const float4*)(keys + (size_t)(n0 + 2) * Dd);
    const float4* __restrict__ k3 = (const float4*)(keys + (size_t)(n0 + 3) * Dd);

    float dot[4][Bb];
    float ssq[4] = {0.f, 0.f, 0.f, 0.f};
    #pragma unroll
    for (int j = 0; j < 4; j++)
        #pragma unroll
        for (int bb = 0; bb < Bb; bb++) dot[j][bb] = 0.f;

    #pragma unroll 2
    for (int i = lane; i < Dd / 4; i += 32) {
        float4 kv[4];
        kv[0] = __ldcs(&k0[i]); kv[1] = __ldcs(&k1[i]);
        kv[2] = __ldcs(&k2[i]); kv[3] = __ldcs(&k3[i]);
        #pragma unroll
        for (int j = 0; j < 4; j++)
            ssq[j] += kv[j].x * kv[j].x + kv[j].y * kv[j].y
                    + kv[j].z * kv[j].z + kv[j].w * kv[j].w;
        #pragma unroll
        for (int bb = 0; bb < Bb; bb++) {
            float4 qv = ((const float4*)(sq + bb * Dd))[i];
            #pragma unroll
            for (int j = 0; j < 4; j++)
                dot[j][bb] += kv[j].x * qv.x + kv[j].y * qv.y
                            + kv[j].z * qv.z + kv[j].w * qv.w;
        }
    }
    #pragma unroll
    for (int o = 16; o > 0; o >>= 1) {
        #pragma unroll
        for (int j = 0; j < 4; j++) {
            ssq[j] += __shfl_down_sync(0xffffffffu, ssq[j], o);
            #pragma unroll
            for (int bb = 0; bb < Bb; bb++)
                dot[j][bb] += __shfl_down_sync(0xffffffffu, dot[j][bb], o);
        }
    }
    if (lane == 0) {
        #pragma unroll
        for (int j = 0; j < 4; j++) {
            float inv = 1.0f / fmaxf(sqrtf(ssq[j]), 1e-12f);
            #pragma unroll
            for (int bb = 0; bb < Bb; bb++) g_sims[bb][n0 + j] = dot[j][bb] * inv;
        }
    }
}

// ---------------------------------------------------------------------------
// Kernel 4: radix-select top-64 (exact 64th-largest via 2-bit binary search on
// order-preserving uint transform), softmax, gated retrieval, last-token add.
// grid Bb x 512. No sorted order needed -> no 64 serial argmax rounds.
// ---------------------------------------------------------------------------
__global__ void __launch_bounds__(512) k_topk_update(
    const unsigned char* __restrict__ mask,
    const float* __restrict__ values, float* __restrict__ out) {
    const int b = blockIdx.x, t = threadIdx.x;
    const int w = t >> 5, lane = t & 31;

    __shared__ int      s_c1, s_c2, s_c3;
    __shared__ int      s_redc[16];
    __shared__ int      s_topi[KTOP];
    __shared__ int      s_eqi[KTOP];
    __shared__ int      s_ngt, s_neq;
    __shared__ unsigned s_umax;
    __shared__ float    s_w[KTOP];
    __shared__ float    s_scale;
    __shared__ int      s_last;

    // ---- mask count (last valid index) ----
    int cnt = 0;
    for (int i = t; i < Ss; i += 512) cnt += (int)mask[b * Ss + i];
    for (int o = 16; o > 0; o >>= 1) cnt += __shfl_down_sync(0xffffffffu, cnt, o);
    if (lane == 0) s_redc[w] = cnt;

    // ---- load sims, transform to order-preserving uint ----
    unsigned u[16];
    #pragma unroll
    for (int j = 0; j < 16; j++) {
        unsigned bits = __float_as_uint(g_sims[b][t + j * 512]);
        u[j] = bits ^ (unsigned)(((int)bits >> 31) | 0x80000000);
    }

    if (t == 0) { s_ngt = 0; s_neq = 0; s_umax = 0; }

    // ---- binary search for exact 64th-largest u (2 bits per round) ----
    unsigned p = 0;
    #pragma unroll 1
    for (int bpos = 30; bpos >= 0; bpos -= 2) {
        if (t == 0) { s_c1 = 0; s_c2 = 0; s_c3 = 0; }
        __syncthreads();
        const unsigned t1 = p + (1u << bpos);
        const unsigned t2 = p + (2u << bpos);
        const unsigned t3 = p + (3u << bpos);
        int c1 = 0, c2 = 0, c3 = 0;
        #pragma unroll
        for (int j = 0; j < 16; j++) {
            c1 += (u[j] >= t1); c2 += (u[j] >= t2); c3 += (u[j] >= t3);
        }
        // pack warp sums: each <= 512 -> 10-bit fields
        int packed = c1 | (c2 << 10) | (c3 << 20);
        #pragma unroll
        for (int o = 16; o > 0; o >>= 1)
            packed += __shfl_down_sync(0xffffffffu, packed, o);
        if (lane == 0) {
            atomicAdd(&s_c1, packed & 1023);
            atomicAdd(&s_c2, (packed >> 10) & 1023);
            atomicAdd(&s_c3, (packed >> 20) & 1023);
        }
        __syncthreads();
        if (s_c3 >= KTOP)      p = t3;
        else if (s_c2 >= KTOP) p = t2;
        else if (s_c1 >= KTOP) p = t1;
        __syncthreads();
    }
    // p == exact 64th-largest u value

    // ---- collect: all u > p, plus (64 - count_gt) of u == p ----
    unsigned local_max = 0;
    #pragma unroll
    for (int j = 0; j < 16; j++) {
        if (u[j] > p) {
            int pos = atomicAdd(&s_ngt, 1);
            s_topi[pos] = t + j * 512;
            if (u[j] > local_max) local_max = u[j];
        } else if (u[j] == p) {
            int pos = atomicAdd(&s_neq, 1);
            if (pos < KTOP) s_eqi[pos] = t + j * 512;
        }
    }
    if (local_max) atomicMax(&s_umax, local_max);
    __syncthreads();
    const int ngt = s_ngt;
    if (t < KTOP - ngt) s_topi[ngt + t] = s_eqi[t];

    // ---- weights + gate + scale + last (single thread + t<64 lanes) ----
    unsigned umax = s_umax > p ? s_umax : p;
    unsigned mb = (umax >> 31) ? (umax ^ 0x80000000u) : ~umax;
    const float fmaxv = __uint_as_float(mb);
    __syncthreads();
    if (t < KTOP) {
        float f = g_sims[b][s_topi[t]];
        s_w[t] = __expf((f - fmaxv) * (1.0f / 0.03f));
    }
    __syncthreads();
    if (t == 0) {
        float sum = 0.f;
        #pragma unroll
        for (int k = 0; k < KTOP; k++) sum += s_w[k];
        float gate = 1.0f / (1.0f + __expf(-(fmaxv - 0.85f) * 40.0f));
        s_scale = 16.0f * gate / sum;
        int tot = 0;
        #pragma unroll
        for (int ww = 0; ww < 16; ww++) tot += s_redc[ww];
        s_last = max(tot, 1) - 1;
    }
    __syncthreads();

    // ---- gather weighted values, update out[b,last,:] ----
    const float scale = s_scale;
    float* __restrict__ op = out + (size_t)b * Ss * Dd + (size_t)s_last * Dd + t * 4;

    float4 acc = make_float4(0.f, 0.f, 0.f, 0.f);
    #pragma unroll 8
    for (int k = 0; k < KTOP; k++) {
        const float4 vv = *(const float4*)(values + (size_t)s_topi[k] * Dd + t * 4);
        const float wk = s_w[k];
        acc.x += wk * vv.x; acc.y += wk * vv.y;
        acc.z += wk * vv.z; acc.w += wk * vv.w;
    }
    float4 cur = *(float4*)op;
    cur.x += scale * acc.x; cur.y += scale * acc.y;
    cur.z += scale * acc.z; cur.w += scale * acc.w;
    *(float4*)op = cur;
}

extern "C" void kernel_launch(void* const* d_in, const int* in_sizes, int n_in,
                              void* d_out, int out_size) {
    const float*         x    = (const float*)d_in[0];
    const unsigned char* mask = (const unsigned char*)d_in[1];
    const float*         keys = (const float*)d_in[2];
    const float*         vals = (const float*)d_in[3];
    float* out = (float*)d_out;

    cudaFuncSetAttribute(k_sims, cudaFuncAttributeMaxDynamicSharedMemorySize,
                         Bb * Dd * (int)sizeof(float));

    k_copy_reduce<<<dim3(Dd / 1024, SCHUNKS, Bb), 256>>>(x, mask, out);
    k_qnorm<<<Bb, 512>>>();
    k_sims<<<256, 256, Bb * Dd * sizeof(float)>>>(keys);
    k_topk_update<<<Bb, 512>>>(mask, vals, out);
}